// round 14
// baseline (speedup 1.0000x reference)
#include <cuda_runtime.h>
#include <cstdint>

#define D_      32
#define K_      40
#define DTOT_   64
#define Bb      5.0f
#define LUTN_   128

// Transposed tables: [bin][dim] — bank depends only on dim (conflict-free gathers).
__device__ float4   g_At  [K_ * D_];     // {mcw = -cumw*ibw, ibw, ch, bh}
__device__ float2   g_B2t [K_ * D_];     // {d0, d1}
__device__ unsigned g_lutp[LUTN_ * D_];  // fp32 edge, idx in low 6 mantissa bits
__device__ int      g_colmap[DTOT_];

#define FULLM 0xffffffffu
__device__ __forceinline__ float warp_max(float v) {
#pragma unroll
    for (int o = 16; o; o >>= 1) v = fmaxf(v, __shfl_xor_sync(FULLM, v, o));
    return v;
}
__device__ __forceinline__ float warp_sum(float v) {
#pragma unroll
    for (int o = 16; o; o >>= 1) v += __shfl_xor_sync(FULLM, v, o);
    return v;
}
__device__ __forceinline__ float warp_scan(float v, int lane) {
#pragma unroll
    for (int o = 1; o < 32; o <<= 1) {
        float t = __shfl_up_sync(FULLM, v, o);
        if (lane >= o) v += t;
    }
    return v;
}

// Warp-per-dim precompute (32 warps).
__global__ void __launch_bounds__(1024)
precompute_tables(const float* __restrict__ w,
                  const float* __restrict__ h,
                  const float* __restrict__ d,
                  const int*   __restrict__ nodes) {
    __shared__ float scumw[D_][K_ + 1];
    const int tid = threadIdx.x, lane = tid & 31, j = tid >> 5;

    if (tid < DTOT_) g_colmap[tid] = -1;
    __syncthreads();
    if (tid < D_) g_colmap[nodes[tid]] = tid;

    // widths
    const float w0 = w[j * K_ + lane];
    const float w1 = (lane < 8) ? w[j * K_ + 32 + lane] : -1e30f;
    float m = warp_max(fmaxf(w0, w1));
    const float e0 = expf(w0 - m);
    const float e1 = (lane < 8) ? expf(w1 - m) : 0.0f;
    const float scl = (2.0f * Bb) / warp_sum(e0 + e1);
    const float bw0 = e0 * scl, bw1 = e1 * scl;
    float s0 = warp_scan(bw0, lane);
    const float tot0 = __shfl_sync(FULLM, s0, 31);
    float s1 = warp_scan(bw1, lane) + tot0;
    const float cw0 = -Bb + s0 - bw0, cw0n = -Bb + s0;
    const float cw1 = -Bb + s1 - bw1, cw1n = -Bb + s1;

    // heights
    const float h0 = h[j * K_ + lane];
    const float h1 = (lane < 8) ? h[j * K_ + 32 + lane] : -1e30f;
    m = warp_max(fmaxf(h0, h1));
    const float f0 = expf(h0 - m);
    const float f1 = (lane < 8) ? expf(h1 - m) : 0.0f;
    const float scl2 = (2.0f * Bb) / warp_sum(f0 + f1);
    const float bh0 = f0 * scl2, bh1 = f1 * scl2;
    float t0 = warp_scan(bh0, lane);
    const float htot0 = __shfl_sync(FULLM, t0, 31);
    float t1 = warp_scan(bh1, lane) + htot0;
    const float ch0 = -Bb + t0 - bh0;
    const float ch1 = -Bb + t1 - bh1;

    // derivatives dv(i) = (i==0||i==K)?1:softplus(d[i-1])
    const float dva0 = (lane == 0) ? 1.0f : log1pf(expf(d[j * (K_ - 1) + lane - 1]));
    const float dvb0 = log1pf(expf(d[j * (K_ - 1) + lane]));
    float dva1 = 0.f, dvb1 = 0.f;
    if (lane < 8) {
        const int i = 32 + lane;
        dva1 = log1pf(expf(d[j * (K_ - 1) + i - 1]));
        dvb1 = (i + 1 == K_) ? 1.0f : log1pf(expf(d[j * (K_ - 1) + i]));
    }

    // transposed stores: [bin][dim]; A.x = -cumw*ibw for 1-FFMA theta
    {
        const float ibw = 1.0f / bw0;
        g_At [lane * D_ + j] = make_float4(-cw0 * ibw, ibw, ch0, bh0);
        g_B2t[lane * D_ + j] = make_float2(dva0, dvb0);
        scumw[j][lane] = cw0;
    }
    if (lane < 8) {
        const int i = 32 + lane;
        const float ibw = 1.0f / bw1;
        g_At [i * D_ + j] = make_float4(-cw1 * ibw, ibw, ch1, bh1);
        g_B2t[i * D_ + j] = make_float2(dva1, dvb1);
        scumw[j][i] = cw1;
        if (i == K_ - 1) scumw[j][K_] = cw1n;
    }
    __syncwarp();

    // LUT: entry[m][j] = fp32(cumw[idx+1]) | idx (low 6 bits); NaN edge on last bin.
    #pragma unroll
    for (int c = 0; c < 4; c++) {
        const int mm = lane * 4 + c;
        const float xm = -Bb + (2.0f * Bb) * ((float)mm / (float)LUTN_);
        int lo = 0, hi = K_;
        while (hi - lo > 1) {
            const int mid = (lo + hi) >> 1;
            if (scumw[j][mid] <= xm) lo = mid; else hi = mid;
        }
        unsigned bits;
        if (lo >= K_ - 1) {
            bits = (0x7fc00000u & ~63u) | (unsigned)(K_ - 1);
        } else {
            const float edge = scumw[j][lo + 1];
            bits = (__float_as_uint(edge) & ~63u) | (unsigned)lo;
        }
        g_lutp[mm * D_ + j] = bits;
    }
}

__device__ __forceinline__ void eval_one(
    float x, int jb, float lim,
    const float4* s_A, const float2* s_B2, const unsigned* s_lutp,
    float& y, float& acc)
{
    const float xc = fminf(fmaxf(x, -Bb), 4.9999995f);
    const int m = (int)fmaf(xc, (float)LUTN_ / (2.0f * Bb), (float)(LUTN_ / 2));
    const unsigned e = s_lutp[m * D_ + jb];
    int idx = (int)(e & 63u);
    const float edge = __uint_as_float(e & ~63u);
    idx += (xc >= edge);          // NaN edge on last bin => never increments

    const float4 A  = s_A [idx * D_ + jb];
    const float2 Bv = s_B2[idx * D_ + jb];
    const float ibw = A.y, bh = A.w;
    const float dlt = bh * ibw;
    const float theta = fmaf(xc, ibw, A.x);
    const float t2  = theta * theta;
    const float t1m = theta - t2;
    const float d0v = Bv.x, d1v = Bv.y;
    const float denom = fmaf(d0v + d1v - 2.0f * dlt, t1m, dlt);
    const float rd  = __fdividef(1.0f, denom);
    const float num = bh * fmaf(dlt, t2, d0v * t1m);
    const float ys  = fmaf(num, rd, A.z);
    const float omt = 1.0f - theta;
    const float At  = fmaf(d1v, t2, fmaf(2.0f * dlt, t1m, d0v * (omt * omt)));
    const float dr  = dlt * rd;
    const float ld  = __logf(dr * dr * At);

    const bool valid = fabsf(x) <= lim;
    y = valid ? ys : x;
    acc += valid ? ld : 0.0f;
}

// Dynamic smem: A(20480) B2(10240) lut(16384) colmap(256)
#define SM_A_ELE  (K_ * D_)
#define SM_B_OFF  (SM_A_ELE * 16)
#define SM_L_OFF  (SM_B_OFF + SM_A_ELE * 8)
#define SM_C_OFF  (SM_L_OFF + LUTN_ * D_ * 4)
#define SM_TOTAL  (SM_C_OFF + DTOT_ * 4)

extern __shared__ unsigned char smem_raw[];

__global__ void __launch_bounds__(512, 4)
spline_kernel(const float* __restrict__ u,
              float* __restrict__ xout,
              float* __restrict__ logd,
              int N) {
    float4*   s_A      = (float4*)smem_raw;
    float2*   s_B2     = (float2*)(smem_raw + SM_B_OFF);
    unsigned* s_lutp   = (unsigned*)(smem_raw + SM_L_OFF);
    int*      s_colmap = (int*)(smem_raw + SM_C_OFF);

    for (int i = threadIdx.x; i < SM_A_ELE; i += blockDim.x) {
        s_A[i]  = g_At[i];
        s_B2[i] = g_B2t[i];
    }
    for (int i = threadIdx.x; i < LUTN_ * D_; i += blockDim.x)
        s_lutp[i] = g_lutp[i];
    if (threadIdx.x < DTOT_) s_colmap[threadIdx.x] = g_colmap[threadIdx.x];
    __syncthreads();

    const int lane = threadIdx.x & 31;
    const int warp = threadIdx.x >> 5;
    const int wpb  = blockDim.x >> 5;

    const int j0 = s_colmap[lane];
    const int j1 = s_colmap[lane + 32];
    const int jb0 = max(j0, 0);
    const int jb1 = max(j1, 0);
    const float lim0 = (j0 >= 0) ? Bb : -1.0f;
    const float lim1 = (j1 >= 0) ? Bb : -1.0f;
    const bool do0 = __any_sync(FULLM, j0 >= 0);
    const bool do1 = __any_sync(FULLM, j1 >= 0);

    const int  stride  = gridDim.x * wpb * 4;     // rows per step (quads)
    const long strideF = (long)stride * DTOT_;

    int row = (blockIdx.x * wpb + warp) * 4;
    const float* pu = u    + (long)row * DTOT_ + lane;
    float*       px = xout + (long)row * DTOT_ + lane;
    float*       pl = logd + row;

    for (; row < N; row += stride, pu += strideF, px += strideF, pl += stride) {
        if (row + 3 < N) {
            // 8 independent streaming loads up front (MLP=8)
            const float a0 = __ldcs(pu +   0), a1 = __ldcs(pu +  32);
            const float b0 = __ldcs(pu +  64), b1 = __ldcs(pu +  96);
            const float c0 = __ldcs(pu + 128), c1 = __ldcs(pu + 160);
            const float d0 = __ldcs(pu + 192), d1 = __ldcs(pu + 224);

            float aa = 0.f, ab = 0.f, ac = 0.f, ad = 0.f;

            // evaluate + store per row immediately (short live ranges)
            {
                float y0 = a0, y1 = a1;
                if (do0) eval_one(a0, jb0, lim0, s_A, s_B2, s_lutp, y0, aa);
                if (do1) eval_one(a1, jb1, lim1, s_A, s_B2, s_lutp, y1, aa);
                __stcs(px +   0, y0); __stcs(px +  32, y1);
            }
            {
                float y0 = b0, y1 = b1;
                if (do0) eval_one(b0, jb0, lim0, s_A, s_B2, s_lutp, y0, ab);
                if (do1) eval_one(b1, jb1, lim1, s_A, s_B2, s_lutp, y1, ab);
                __stcs(px +  64, y0); __stcs(px +  96, y1);
            }
            {
                float y0 = c0, y1 = c1;
                if (do0) eval_one(c0, jb0, lim0, s_A, s_B2, s_lutp, y0, ac);
                if (do1) eval_one(c1, jb1, lim1, s_A, s_B2, s_lutp, y1, ac);
                __stcs(px + 128, y0); __stcs(px + 160, y1);
            }
            {
                float y0 = d0, y1 = d1;
                if (do0) eval_one(d0, jb0, lim0, s_A, s_B2, s_lutp, y0, ad);
                if (do1) eval_one(d1, jb1, lim1, s_A, s_B2, s_lutp, y1, ad);
                __stcs(px + 192, y0); __stcs(px + 224, y1);
            }

            // paired reductions (5 shfls per pair)
            {
                float v = (lane < 16) ? ab : aa;
                float t = __shfl_xor_sync(FULLM, v, 16);
                float r = ((lane < 16) ? aa : ab) + t;
#pragma unroll
                for (int o = 8; o; o >>= 1) r += __shfl_xor_sync(FULLM, r, o);
                if (lane == 0)  __stcs(pl + 0, r);
                if (lane == 16) __stcs(pl + 1, r);
            }
            {
                float v = (lane < 16) ? ad : ac;
                float t = __shfl_xor_sync(FULLM, v, 16);
                float r = ((lane < 16) ? ac : ad) + t;
#pragma unroll
                for (int o = 8; o; o >>= 1) r += __shfl_xor_sync(FULLM, r, o);
                if (lane == 0)  __stcs(pl + 2, r);
                if (lane == 16) __stcs(pl + 3, r);
            }
        } else {
            // tail: per-row guarded
            for (int r = 0; r < 4 && row + r < N; r++) {
                const float x0 = pu[r * 64];
                const float x1 = pu[r * 64 + 32];
                float acc = 0.f, y0 = x0, y1 = x1;
                if (do0) eval_one(x0, jb0, lim0, s_A, s_B2, s_lutp, y0, acc);
                if (do1) eval_one(x1, jb1, lim1, s_A, s_B2, s_lutp, y1, acc);
                px[r * 64]      = y0;
                px[r * 64 + 32] = y1;
#pragma unroll
                for (int o = 16; o; o >>= 1) acc += __shfl_xor_sync(FULLM, acc, o);
                if (lane == 0) pl[r] = acc;
            }
        }
    }
}

extern "C" void kernel_launch(void* const* d_in, const int* in_sizes, int n_in,
                              void* d_out, int out_size) {
    const float* u     = (const float*)d_in[0];
    const float* w     = (const float*)d_in[1];
    const float* h     = (const float*)d_in[2];
    const float* d     = (const float*)d_in[3];
    const int*   nodes = (const int*)  d_in[4];

    const int N = out_size - in_sizes[0];
    float* xout = (float*)d_out;
    float* logd = xout + (size_t)N * DTOT_;

    static int smem_set = 0;
    if (!smem_set) {
        cudaFuncSetAttribute(spline_kernel,
                             cudaFuncAttributeMaxDynamicSharedMemorySize, SM_TOTAL);
        smem_set = 1;
    }

    precompute_tables<<<1, 1024>>>(w, h, d, nodes);
    spline_kernel<<<592, 512, SM_TOTAL>>>(u, xout, logd, N);
}

// round 16
// speedup vs baseline: 1.1305x; 1.1305x over previous
#include <cuda_runtime.h>
#include <cstdint>

#define D_      32
#define K_      40
#define DTOT_   64
#define Bb      5.0f
#define LUTN_   128

#define FULLM 0xffffffffu
__device__ __forceinline__ float warp_max(float v) {
#pragma unroll
    for (int o = 16; o; o >>= 1) v = fmaxf(v, __shfl_xor_sync(FULLM, v, o));
    return v;
}
__device__ __forceinline__ float warp_sum(float v) {
#pragma unroll
    for (int o = 16; o; o >>= 1) v += __shfl_xor_sync(FULLM, v, o);
    return v;
}
__device__ __forceinline__ float warp_scan(float v, int lane) {
#pragma unroll
    for (int o = 1; o < 32; o <<= 1) {
        float t = __shfl_up_sync(FULLM, v, o);
        if (lane >= o) v += t;
    }
    return v;
}

__device__ __forceinline__ void eval_one(
    float x, int jb, float lim,
    const float4* s_A, const float2* s_B2, const unsigned* s_lutp,
    float& y, float& acc)
{
    const float xc = fminf(fmaxf(x, -Bb), 4.9999995f);
    const int m = (int)fmaf(xc, (float)LUTN_ / (2.0f * Bb), (float)(LUTN_ / 2));
    const unsigned e = s_lutp[m * D_ + jb];
    int idx = (int)(e & 63u);
    const float edge = __uint_as_float(e & ~63u);
    idx += (xc >= edge);          // NaN edge on last bin => never increments

    const float4 A  = s_A [idx * D_ + jb];
    const float2 Bv = s_B2[idx * D_ + jb];
    const float ibw = A.y, bh = A.w;
    const float dlt = bh * ibw;
    const float theta = fmaf(xc, ibw, A.x);
    const float t2  = theta * theta;
    const float t1m = theta - t2;
    const float d0v = Bv.x, d1v = Bv.y;
    const float denom = fmaf(d0v + d1v - 2.0f * dlt, t1m, dlt);
    const float rd  = __fdividef(1.0f, denom);
    const float num = bh * fmaf(dlt, t2, d0v * t1m);
    const float ys  = fmaf(num, rd, A.z);
    const float omt = 1.0f - theta;
    const float At  = fmaf(d1v, t2, fmaf(2.0f * dlt, t1m, d0v * (omt * omt)));
    const float dr  = dlt * rd;
    const float ld  = __logf(dr * dr * At);

    const bool valid = fabsf(x) <= lim;
    y = valid ? ys : x;
    acc += valid ? ld : 0.0f;
}

// Dynamic smem: A(20480) B2(10240) lut(16384) colmap(256) cumw(32*41*4)
#define SM_A_ELE  (K_ * D_)
#define SM_B_OFF  (SM_A_ELE * 16)
#define SM_L_OFF  (SM_B_OFF + SM_A_ELE * 8)
#define SM_C_OFF  (SM_L_OFF + LUTN_ * D_ * 4)
#define SM_W_OFF  (SM_C_OFF + DTOT_ * 4)
#define SM_TOTAL  (SM_W_OFF + D_ * (K_ + 1) * 4)

extern __shared__ unsigned char smem_raw[];

__global__ void __launch_bounds__(512, 3)
spline_kernel(const float* __restrict__ u,
              const float* __restrict__ wp,
              const float* __restrict__ hp,
              const float* __restrict__ dp,
              const int*   __restrict__ nodes,
              float* __restrict__ xout,
              float* __restrict__ logd,
              int N) {
    float4*   s_A      = (float4*)smem_raw;
    float2*   s_B2     = (float2*)(smem_raw + SM_B_OFF);
    unsigned* s_lutp   = (unsigned*)(smem_raw + SM_L_OFF);
    int*      s_colmap = (int*)(smem_raw + SM_C_OFF);
    float*    s_cumw   = (float*)(smem_raw + SM_W_OFF);   // [D_][K_+1]

    const int tid  = threadIdx.x;
    const int lane = tid & 31;
    const int warp = tid >> 5;
    const int wpb  = blockDim.x >> 5;

    // ================= in-block table build ==================================
    if (tid < DTOT_) s_colmap[tid] = -1;
    __syncthreads();
    if (tid < D_) s_colmap[nodes[tid]] = tid;

    // each warp builds 2 dims (16 warps x 2 = 32 dims)
    for (int j = warp * 2; j < warp * 2 + 2; j++) {
        // widths
        const float w0 = wp[j * K_ + lane];
        const float w1 = (lane < 8) ? wp[j * K_ + 32 + lane] : -1e30f;
        float m = warp_max(fmaxf(w0, w1));
        const float e0 = expf(w0 - m);
        const float e1 = (lane < 8) ? expf(w1 - m) : 0.0f;
        const float scl = (2.0f * Bb) / warp_sum(e0 + e1);
        const float bw0 = e0 * scl, bw1 = e1 * scl;
        float s0 = warp_scan(bw0, lane);
        const float tot0 = __shfl_sync(FULLM, s0, 31);
        float s1 = warp_scan(bw1, lane) + tot0;
        const float cw0 = -Bb + s0 - bw0;
        const float cw1 = -Bb + s1 - bw1, cw1n = -Bb + s1;

        // heights
        const float h0 = hp[j * K_ + lane];
        const float h1 = (lane < 8) ? hp[j * K_ + 32 + lane] : -1e30f;
        m = warp_max(fmaxf(h0, h1));
        const float f0 = expf(h0 - m);
        const float f1 = (lane < 8) ? expf(h1 - m) : 0.0f;
        const float scl2 = (2.0f * Bb) / warp_sum(f0 + f1);
        const float bh0 = f0 * scl2, bh1 = f1 * scl2;
        float t0 = warp_scan(bh0, lane);
        const float htot0 = __shfl_sync(FULLM, t0, 31);
        float t1 = warp_scan(bh1, lane) + htot0;
        const float ch0 = -Bb + t0 - bh0;
        const float ch1 = -Bb + t1 - bh1;

        // derivatives dv(i) = (i==0||i==K)?1:softplus(d[i-1])
        const float dva0 = (lane == 0) ? 1.0f : log1pf(expf(dp[j * (K_ - 1) + lane - 1]));
        const float dvb0 = log1pf(expf(dp[j * (K_ - 1) + lane]));
        float dva1 = 0.f, dvb1 = 0.f;
        if (lane < 8) {
            const int i = 32 + lane;
            dva1 = log1pf(expf(dp[j * (K_ - 1) + i - 1]));
            dvb1 = (i + 1 == K_) ? 1.0f : log1pf(expf(dp[j * (K_ - 1) + i]));
        }

        // transposed stores: [bin][dim]; A.x = -cumw*ibw for 1-FFMA theta
        {
            const float ibw = 1.0f / bw0;
            s_A [lane * D_ + j] = make_float4(-cw0 * ibw, ibw, ch0, bh0);
            s_B2[lane * D_ + j] = make_float2(dva0, dvb0);
            s_cumw[j * (K_ + 1) + lane] = cw0;
        }
        if (lane < 8) {
            const int i = 32 + lane;
            const float ibw = 1.0f / bw1;
            s_A [i * D_ + j] = make_float4(-cw1 * ibw, ibw, ch1, bh1);
            s_B2[i * D_ + j] = make_float2(dva1, dvb1);
            s_cumw[j * (K_ + 1) + i] = cw1;
            if (i == K_ - 1) s_cumw[j * (K_ + 1) + K_] = cw1n;
        }
    }
    __syncthreads();

    // LUT: 4096 entries / 512 threads = 8 each; binary search over cumw
    for (int t = tid; t < LUTN_ * D_; t += blockDim.x) {
        const int j  = t & (D_ - 1);        // dim
        const int mm = t >> 5;              // cell
        const float xm = -Bb + (2.0f * Bb) * ((float)mm / (float)LUTN_);
        const float* cw = &s_cumw[j * (K_ + 1)];
        int lo = 0, hi = K_;
        while (hi - lo > 1) {
            const int mid = (lo + hi) >> 1;
            if (cw[mid] <= xm) lo = mid; else hi = mid;
        }
        unsigned bits;
        if (lo >= K_ - 1) {
            bits = (0x7fc00000u & ~63u) | (unsigned)(K_ - 1);  // NaN edge, idx=K-1
        } else {
            bits = (__float_as_uint(cw[lo + 1]) & ~63u) | (unsigned)lo;
        }
        s_lutp[mm * D_ + j] = bits;
    }
    __syncthreads();

    // ================= main loop (R11 structure) =============================
    const int j0 = s_colmap[lane];
    const int j1 = s_colmap[lane + 32];
    const int jb0 = max(j0, 0);
    const int jb1 = max(j1, 0);
    const float lim0 = (j0 >= 0) ? Bb : -1.0f;
    const float lim1 = (j1 >= 0) ? Bb : -1.0f;
    const bool do0 = __any_sync(FULLM, j0 >= 0);
    const bool do1 = __any_sync(FULLM, j1 >= 0);

    const int  stride  = gridDim.x * wpb * 4;     // rows per step (quads)
    const long strideF = (long)stride * DTOT_;

    int row = (blockIdx.x * wpb + warp) * 4;
    const float* pu = u    + (long)row * DTOT_ + lane;
    float*       px = xout + (long)row * DTOT_ + lane;
    float*       pl = logd + row;

    for (; row < N; row += stride, pu += strideF, px += strideF, pl += stride) {
        if (row + 3 < N) {
            // 8 independent loads up front (MLP=8)
            const float a0 = pu[0],   a1 = pu[32];
            const float b0 = pu[64],  b1 = pu[96];
            const float c0 = pu[128], c1 = pu[160];
            const float d0 = pu[192], d1 = pu[224];

            float aa = 0.f, ab = 0.f, ac = 0.f, ad = 0.f;
            float ya0 = a0, ya1 = a1, yb0 = b0, yb1 = b1;
            float yc0 = c0, yc1 = c1, yd0 = d0, yd1 = d1;

            if (do0) {
                eval_one(a0, jb0, lim0, s_A, s_B2, s_lutp, ya0, aa);
                eval_one(b0, jb0, lim0, s_A, s_B2, s_lutp, yb0, ab);
                eval_one(c0, jb0, lim0, s_A, s_B2, s_lutp, yc0, ac);
                eval_one(d0, jb0, lim0, s_A, s_B2, s_lutp, yd0, ad);
            }
            if (do1) {
                eval_one(a1, jb1, lim1, s_A, s_B2, s_lutp, ya1, aa);
                eval_one(b1, jb1, lim1, s_A, s_B2, s_lutp, yb1, ab);
                eval_one(c1, jb1, lim1, s_A, s_B2, s_lutp, yc1, ac);
                eval_one(d1, jb1, lim1, s_A, s_B2, s_lutp, yd1, ad);
            }

            px[0]   = ya0;  px[32]  = ya1;
            px[64]  = yb0;  px[96]  = yb1;
            px[128] = yc0;  px[160] = yc1;
            px[192] = yd0;  px[224] = yd1;

            // paired reductions (5 shfls per pair)
            {
                float v = (lane < 16) ? ab : aa;
                float t = __shfl_xor_sync(FULLM, v, 16);
                float r = ((lane < 16) ? aa : ab) + t;
#pragma unroll
                for (int o = 8; o; o >>= 1) r += __shfl_xor_sync(FULLM, r, o);
                if (lane == 0)  pl[0] = r;
                if (lane == 16) pl[1] = r;
            }
            {
                float v = (lane < 16) ? ad : ac;
                float t = __shfl_xor_sync(FULLM, v, 16);
                float r = ((lane < 16) ? ac : ad) + t;
#pragma unroll
                for (int o = 8; o; o >>= 1) r += __shfl_xor_sync(FULLM, r, o);
                if (lane == 0)  pl[2] = r;
                if (lane == 16) pl[3] = r;
            }
        } else {
            // tail: per-row guarded
            for (int r = 0; r < 4 && row + r < N; r++) {
                const float x0 = pu[r * 64];
                const float x1 = pu[r * 64 + 32];
                float acc = 0.f, y0 = x0, y1 = x1;
                if (do0) eval_one(x0, jb0, lim0, s_A, s_B2, s_lutp, y0, acc);
                if (do1) eval_one(x1, jb1, lim1, s_A, s_B2, s_lutp, y1, acc);
                px[r * 64]      = y0;
                px[r * 64 + 32] = y1;
#pragma unroll
                for (int o = 16; o; o >>= 1) acc += __shfl_xor_sync(FULLM, acc, o);
                if (lane == 0) pl[r] = acc;
            }
        }
    }
}

extern "C" void kernel_launch(void* const* d_in, const int* in_sizes, int n_in,
                              void* d_out, int out_size) {
    const float* u     = (const float*)d_in[0];
    const float* w     = (const float*)d_in[1];
    const float* h     = (const float*)d_in[2];
    const float* d     = (const float*)d_in[3];
    const int*   nodes = (const int*)  d_in[4];

    const int N = out_size - in_sizes[0];
    float* xout = (float*)d_out;
    float* logd = xout + (size_t)N * DTOT_;

    static int smem_set = 0;
    if (!smem_set) {
        cudaFuncSetAttribute(spline_kernel,
                             cudaFuncAttributeMaxDynamicSharedMemorySize, SM_TOTAL);
        smem_set = 1;
    }

    spline_kernel<<<444, 512, SM_TOTAL>>>(u, w, h, d, nodes, xout, logd, N);
}

// round 17
// speedup vs baseline: 1.1444x; 1.0123x over previous
#include <cuda_runtime.h>
#include <cstdint>

#define D_      32
#define K_      40
#define DTOT_   64
#define Bb      5.0f
#define LUTN_   128

#define FULLM 0xffffffffu
__device__ __forceinline__ float warp_max(float v) {
#pragma unroll
    for (int o = 16; o; o >>= 1) v = fmaxf(v, __shfl_xor_sync(FULLM, v, o));
    return v;
}
__device__ __forceinline__ float warp_sum(float v) {
#pragma unroll
    for (int o = 16; o; o >>= 1) v += __shfl_xor_sync(FULLM, v, o);
    return v;
}
__device__ __forceinline__ float warp_scan(float v, int lane) {
#pragma unroll
    for (int o = 1; o < 32; o <<= 1) {
        float t = __shfl_up_sync(FULLM, v, o);
        if (lane >= o) v += t;
    }
    return v;
}

// fast softplus: x in [-0.5, 0.5] here, no overflow concerns
__device__ __forceinline__ float softplus_fast(float x) {
    return __logf(1.0f + __expf(x));
}

__device__ __forceinline__ void eval_one(
    float x, int jb, float lim,
    const float4* s_A, const float2* s_B2, const unsigned* s_lutp,
    float& y, float& acc)
{
    const float xc = fminf(fmaxf(x, -Bb), 4.9999995f);
    const int m = (int)fmaf(xc, (float)LUTN_ / (2.0f * Bb), (float)(LUTN_ / 2));
    const unsigned e = s_lutp[m * D_ + jb];
    int idx = (int)(e & 63u);
    const float edge = __uint_as_float(e & ~63u);
    idx += (xc >= edge);          // NaN edge on last bin => never increments

    const float4 A  = s_A [idx * D_ + jb];
    const float2 Bv = s_B2[idx * D_ + jb];
    const float ibw = A.y, bh = A.w;
    const float dlt = bh * ibw;
    const float theta = fmaf(xc, ibw, A.x);
    const float t2  = theta * theta;
    const float t1m = theta - t2;
    const float d0v = Bv.x, d1v = Bv.y;
    const float denom = fmaf(d0v + d1v - 2.0f * dlt, t1m, dlt);
    const float rd  = __fdividef(1.0f, denom);
    const float num = bh * fmaf(dlt, t2, d0v * t1m);
    const float ys  = fmaf(num, rd, A.z);
    const float omt = 1.0f - theta;
    const float At  = fmaf(d1v, t2, fmaf(2.0f * dlt, t1m, d0v * (omt * omt)));
    const float dr  = dlt * rd;
    const float ld  = __logf(dr * dr * At);

    const bool valid = fabsf(x) <= lim;
    y = valid ? ys : x;
    acc += valid ? ld : 0.0f;
}

// Dynamic smem: A(20480) B2(10240) lut(16384) colmap(256) cumw(32*41*4)
#define SM_A_ELE  (K_ * D_)
#define SM_B_OFF  (SM_A_ELE * 16)
#define SM_L_OFF  (SM_B_OFF + SM_A_ELE * 8)
#define SM_C_OFF  (SM_L_OFF + LUTN_ * D_ * 4)
#define SM_W_OFF  (SM_C_OFF + DTOT_ * 4)
#define SM_TOTAL  (SM_W_OFF + D_ * (K_ + 1) * 4)

extern __shared__ unsigned char smem_raw[];

__global__ void __launch_bounds__(512, 3)
spline_kernel(const float* __restrict__ u,
              const float* __restrict__ wp,
              const float* __restrict__ hp,
              const float* __restrict__ dp,
              const int*   __restrict__ nodes,
              float* __restrict__ xout,
              float* __restrict__ logd,
              int N) {
    float4*   s_A      = (float4*)smem_raw;
    float2*   s_B2     = (float2*)(smem_raw + SM_B_OFF);
    unsigned* s_lutp   = (unsigned*)(smem_raw + SM_L_OFF);
    int*      s_colmap = (int*)(smem_raw + SM_C_OFF);
    float*    s_cumw   = (float*)(smem_raw + SM_W_OFF);   // [D_][K_+1]

    const int tid  = threadIdx.x;
    const int lane = tid & 31;
    const int warp = tid >> 5;
    const int wpb  = blockDim.x >> 5;

    // ================= in-block table build (fast math) ======================
    if (tid < DTOT_) s_colmap[tid] = -1;
    __syncthreads();
    if (tid < D_) s_colmap[nodes[tid]] = tid;

    // each warp builds 2 dims (16 warps x 2 = 32 dims)
    for (int j = warp * 2; j < warp * 2 + 2; j++) {
        // widths
        const float w0 = wp[j * K_ + lane];
        const float w1 = (lane < 8) ? wp[j * K_ + 32 + lane] : -1e30f;
        float m = warp_max(fmaxf(w0, w1));
        const float e0 = __expf(w0 - m);
        const float e1 = (lane < 8) ? __expf(w1 - m) : 0.0f;
        const float scl = (2.0f * Bb) / warp_sum(e0 + e1);
        const float bw0 = e0 * scl, bw1 = e1 * scl;
        float s0 = warp_scan(bw0, lane);
        const float tot0 = __shfl_sync(FULLM, s0, 31);
        float s1 = warp_scan(bw1, lane) + tot0;
        const float cw0 = -Bb + s0 - bw0;
        const float cw1 = -Bb + s1 - bw1, cw1n = -Bb + s1;

        // heights
        const float h0 = hp[j * K_ + lane];
        const float h1 = (lane < 8) ? hp[j * K_ + 32 + lane] : -1e30f;
        m = warp_max(fmaxf(h0, h1));
        const float f0 = __expf(h0 - m);
        const float f1 = (lane < 8) ? __expf(h1 - m) : 0.0f;
        const float scl2 = (2.0f * Bb) / warp_sum(f0 + f1);
        const float bh0 = f0 * scl2, bh1 = f1 * scl2;
        float t0 = warp_scan(bh0, lane);
        const float htot0 = __shfl_sync(FULLM, t0, 31);
        float t1 = warp_scan(bh1, lane) + htot0;
        const float ch0 = -Bb + t0 - bh0;
        const float ch1 = -Bb + t1 - bh1;

        // derivatives dv(i) = (i==0||i==K)?1:softplus(d[i-1])
        const float dva0 = (lane == 0) ? 1.0f : softplus_fast(dp[j * (K_ - 1) + lane - 1]);
        const float dvb0 = softplus_fast(dp[j * (K_ - 1) + lane]);
        float dva1 = 0.f, dvb1 = 0.f;
        if (lane < 8) {
            const int i = 32 + lane;
            dva1 = softplus_fast(dp[j * (K_ - 1) + i - 1]);
            dvb1 = (i + 1 == K_) ? 1.0f : softplus_fast(dp[j * (K_ - 1) + i]);
        }

        // transposed stores: [bin][dim]; A.x = -cumw*ibw for 1-FFMA theta
        {
            const float ibw = 1.0f / bw0;
            s_A [lane * D_ + j] = make_float4(-cw0 * ibw, ibw, ch0, bh0);
            s_B2[lane * D_ + j] = make_float2(dva0, dvb0);
            s_cumw[j * (K_ + 1) + lane] = cw0;
        }
        if (lane < 8) {
            const int i = 32 + lane;
            const float ibw = 1.0f / bw1;
            s_A [i * D_ + j] = make_float4(-cw1 * ibw, ibw, ch1, bh1);
            s_B2[i * D_ + j] = make_float2(dva1, dvb1);
            s_cumw[j * (K_ + 1) + i] = cw1;
            if (i == K_ - 1) s_cumw[j * (K_ + 1) + K_] = cw1n;
        }
    }
    __syncthreads();

    // LUT: 4096 entries / 512 threads = 8 each; binary search over cumw
    for (int t = tid; t < LUTN_ * D_; t += blockDim.x) {
        const int j  = t & (D_ - 1);        // dim
        const int mm = t >> 5;              // cell
        const float xm = -Bb + (2.0f * Bb) * ((float)mm / (float)LUTN_);
        const float* cw = &s_cumw[j * (K_ + 1)];
        int lo = 0, hi = K_;
        while (hi - lo > 1) {
            const int mid = (lo + hi) >> 1;
            if (cw[mid] <= xm) lo = mid; else hi = mid;
        }
        unsigned bits;
        if (lo >= K_ - 1) {
            bits = (0x7fc00000u & ~63u) | (unsigned)(K_ - 1);  // NaN edge, idx=K-1
        } else {
            bits = (__float_as_uint(cw[lo + 1]) & ~63u) | (unsigned)lo;
        }
        s_lutp[mm * D_ + j] = bits;
    }
    __syncthreads();

    // ================= main loop (R11 structure) =============================
    const int j0 = s_colmap[lane];
    const int j1 = s_colmap[lane + 32];
    const int jb0 = max(j0, 0);
    const int jb1 = max(j1, 0);
    const float lim0 = (j0 >= 0) ? Bb : -1.0f;
    const float lim1 = (j1 >= 0) ? Bb : -1.0f;
    const bool do0 = __any_sync(FULLM, j0 >= 0);
    const bool do1 = __any_sync(FULLM, j1 >= 0);

    const int  stride  = gridDim.x * wpb * 4;     // rows per step (quads)
    const long strideF = (long)stride * DTOT_;

    int row = (blockIdx.x * wpb + warp) * 4;
    const float* pu = u    + (long)row * DTOT_ + lane;
    float*       px = xout + (long)row * DTOT_ + lane;
    float*       pl = logd + row;

    for (; row < N; row += stride, pu += strideF, px += strideF, pl += stride) {
        if (row + 3 < N) {
            // 8 independent loads up front (MLP=8)
            const float a0 = pu[0],   a1 = pu[32];
            const float b0 = pu[64],  b1 = pu[96];
            const float c0 = pu[128], c1 = pu[160];
            const float d0 = pu[192], d1 = pu[224];

            float aa = 0.f, ab = 0.f, ac = 0.f, ad = 0.f;
            float ya0 = a0, ya1 = a1, yb0 = b0, yb1 = b1;
            float yc0 = c0, yc1 = c1, yd0 = d0, yd1 = d1;

            if (do0) {
                eval_one(a0, jb0, lim0, s_A, s_B2, s_lutp, ya0, aa);
                eval_one(b0, jb0, lim0, s_A, s_B2, s_lutp, yb0, ab);
                eval_one(c0, jb0, lim0, s_A, s_B2, s_lutp, yc0, ac);
                eval_one(d0, jb0, lim0, s_A, s_B2, s_lutp, yd0, ad);
            }
            if (do1) {
                eval_one(a1, jb1, lim1, s_A, s_B2, s_lutp, ya1, aa);
                eval_one(b1, jb1, lim1, s_A, s_B2, s_lutp, yb1, ab);
                eval_one(c1, jb1, lim1, s_A, s_B2, s_lutp, yc1, ac);
                eval_one(d1, jb1, lim1, s_A, s_B2, s_lutp, yd1, ad);
            }

            px[0]   = ya0;  px[32]  = ya1;
            px[64]  = yb0;  px[96]  = yb1;
            px[128] = yc0;  px[160] = yc1;
            px[192] = yd0;  px[224] = yd1;

            // paired reductions (5 shfls per pair)
            {
                float v = (lane < 16) ? ab : aa;
                float t = __shfl_xor_sync(FULLM, v, 16);
                float r = ((lane < 16) ? aa : ab) + t;
#pragma unroll
                for (int o = 8; o; o >>= 1) r += __shfl_xor_sync(FULLM, r, o);
                if (lane == 0)  pl[0] = r;
                if (lane == 16) pl[1] = r;
            }
            {
                float v = (lane < 16) ? ad : ac;
                float t = __shfl_xor_sync(FULLM, v, 16);
                float r = ((lane < 16) ? ac : ad) + t;
#pragma unroll
                for (int o = 8; o; o >>= 1) r += __shfl_xor_sync(FULLM, r, o);
                if (lane == 0)  pl[2] = r;
                if (lane == 16) pl[3] = r;
            }
        } else {
            // tail: per-row guarded
            for (int r = 0; r < 4 && row + r < N; r++) {
                const float x0 = pu[r * 64];
                const float x1 = pu[r * 64 + 32];
                float acc = 0.f, y0 = x0, y1 = x1;
                if (do0) eval_one(x0, jb0, lim0, s_A, s_B2, s_lutp, y0, acc);
                if (do1) eval_one(x1, jb1, lim1, s_A, s_B2, s_lutp, y1, acc);
                px[r * 64]      = y0;
                px[r * 64 + 32] = y1;
#pragma unroll
                for (int o = 16; o; o >>= 1) acc += __shfl_xor_sync(FULLM, acc, o);
                if (lane == 0) pl[r] = acc;
            }
        }
    }
}

extern "C" void kernel_launch(void* const* d_in, const int* in_sizes, int n_in,
                              void* d_out, int out_size) {
    const float* u     = (const float*)d_in[0];
    const float* w     = (const float*)d_in[1];
    const float* h     = (const float*)d_in[2];
    const float* d     = (const float*)d_in[3];
    const int*   nodes = (const int*)  d_in[4];

    const int N = out_size - in_sizes[0];
    float* xout = (float*)d_out;
    float* logd = xout + (size_t)N * DTOT_;

    static int smem_set = 0;
    if (!smem_set) {
        cudaFuncSetAttribute(spline_kernel,
                             cudaFuncAttributeMaxDynamicSharedMemorySize, SM_TOTAL);
        smem_set = 1;
    }

    spline_kernel<<<444, 512, SM_TOTAL>>>(u, w, h, d, nodes, xout, logd, N);
}